// round 2
// baseline (speedup 1.0000x reference)
#include <cuda_runtime.h>

#define HW    512
#define IMG   (HW*HW)          // 262144
#define BATCH 32
#define NTOT  (BATCH*IMG)      // 8388608
#define RBLK  2048             // reduction blocks (fixed for determinism)

// Scratch: __device__ globals (no allocation allowed in kernel_launch)
__device__ float  g_prob[NTOT];        // sigmoid(pred)
__device__ float  g_skel[2*NTOT];      // skel for stream 0 (pred) / 1 (target)
__device__ float  g_bufA[2*NTOT];      // erode ping
__device__ float  g_bufB[2*NTOT];      // erode pong
__device__ double g_part[RBLK*4];      // reduction partials

__device__ __forceinline__ int clampi(int v) {
    return v < 0 ? 0 : (v > HW-1 ? HW-1 : v);
}

// ---------------------------------------------------------------------------
// sigmoid: prob = 1/(1+exp(-pred)), vectorized float4
// ---------------------------------------------------------------------------
__global__ void sigmoid_kernel(const float* __restrict__ in, float* __restrict__ out) {
    int i = blockIdx.x * blockDim.x + threadIdx.x;
    int stride = gridDim.x * blockDim.x;
    const float4* in4 = (const float4*)in;
    float4* out4 = (float4*)out;
    for (; i < NTOT/4; i += stride) {
        float4 v = in4[i];
        v.x = 1.f / (1.f + __expf(-v.x));
        v.y = 1.f / (1.f + __expf(-v.y));
        v.z = 1.f / (1.f + __expf(-v.z));
        v.w = 1.f / (1.f + __expf(-v.w));
        out4[i] = v;
    }
}

// ---------------------------------------------------------------------------
// Fused skeleton iteration:
//   e     = erode(X)            (5-pt cross min)
//   d     = dilate(e)           (3x3 max, separable)
//   delta = relu(X - d)
//   first: skel  = delta
//   else : skel += relu(delta - skel*delta)
//   eout  = e                   (becomes next X)
// Boundary: clamp-to-edge == SAME padding with inf identity (idempotent min/max).
// The dilate halo needs e at *clamped* positions (erode-at-clamped), handled by
// computing each e entry at its clamped global coordinate.
// grid: (16,16,64) where z = b*2+s; block: (32,32)
// ---------------------------------------------------------------------------
__global__ __launch_bounds__(1024, 2)
void skel_iter(const float* __restrict__ x0, const float* __restrict__ x1,
               float* __restrict__ skel, float* __restrict__ eout, int first)
{
    __shared__ float sx[36][36];   // X tile, halo 2
    __shared__ float se[34][34];   // erode tile, halo 1
    __shared__ float vm[32][34];   // vertical max of se

    const int s = blockIdx.z & 1;
    const int b = blockIdx.z >> 1;
    const float* X  = (s ? x1 : x0) + (size_t)b * IMG;
    float*       SK = skel + (size_t)s * NTOT + (size_t)b * IMG;
    float*       EO = eout + (size_t)s * NTOT + (size_t)b * IMG;

    const int bx0 = blockIdx.x * 32;
    const int by0 = blockIdx.y * 32;
    const int tid = threadIdx.y * 32 + threadIdx.x;

    // Stage 0: load X tile (clamped)
    for (int i = tid; i < 36*36; i += 1024) {
        int ly = i / 36, lx = i % 36;
        int gy = clampi(by0 - 2 + ly);
        int gx = clampi(bx0 - 2 + lx);
        sx[ly][lx] = X[gy * HW + gx];
    }
    __syncthreads();

    // Stage 1: erode at clamped coordinates (34x34, halo 1 for dilate)
    for (int i = tid; i < 34*34; i += 1024) {
        int ey = i / 34, ex = i % 34;
        int gy = clampi(by0 - 1 + ey);
        int gx = clampi(bx0 - 1 + ex);
        int ly  = gy - (by0 - 2),          lx  = gx - (bx0 - 2);
        int lym = clampi(gy - 1) - (by0-2), lyp = clampi(gy + 1) - (by0-2);
        int lxm = clampi(gx - 1) - (bx0-2), lxp = clampi(gx + 1) - (bx0-2);
        float c = sx[ly][lx];
        float v = fminf(fminf(sx[lym][lx], c), sx[lyp][lx]);
        float h = fminf(fminf(sx[ly][lxm], c), sx[ly][lxp]);
        se[ey][ex] = fminf(v, h);
    }
    __syncthreads();

    // Stage 2: vertical 3-max of e
    for (int i = tid; i < 32*34; i += 1024) {
        int vy = i / 34, vx = i % 34;
        vm[vy][vx] = fmaxf(fmaxf(se[vy][vx], se[vy+1][vx]), se[vy+2][vx]);
    }
    __syncthreads();

    // Stage 3: horizontal 3-max -> dilate; delta; skel update; write e
    const int tx = threadIdx.x, ty = threadIdx.y;
    float d  = fmaxf(fmaxf(vm[ty][tx], vm[ty][tx+1]), vm[ty][tx+2]);
    float xc = sx[ty+2][tx+2];
    float ec = se[ty+1][tx+1];
    float delta = fmaxf(xc - d, 0.f);
    int idx = (by0 + ty) * HW + (bx0 + tx);
    if (first) {
        SK[idx] = delta;
    } else {
        float s0 = SK[idx];
        // relu(delta - s0*delta) = relu(delta*(1-s0))
        SK[idx] = s0 + fmaxf(fmaf(-s0, delta, delta), 0.f);
    }
    EO[idx] = ec;
}

// ---------------------------------------------------------------------------
// Reduction stage 1: 4 sums -> per-block fp64 partials (fixed grid, deterministic)
// ---------------------------------------------------------------------------
__global__ void reduce_kernel(const float* __restrict__ skp, const float* __restrict__ tgt,
                              const float* __restrict__ skt, const float* __restrict__ prob)
{
    __shared__ double sh0[256], sh1[256], sh2[256], sh3[256];
    double a0 = 0, a1 = 0, a2 = 0, a3 = 0;
    int i = blockIdx.x * blockDim.x + threadIdx.x;
    int stride = gridDim.x * blockDim.x;
    for (; i < NTOT; i += stride) {
        float sp = skp[i], st = skt[i];
        a0 += (double)sp;
        a1 += (double)sp * (double)tgt[i];
        a2 += (double)st;
        a3 += (double)st * (double)prob[i];
    }
    int t = threadIdx.x;
    sh0[t] = a0; sh1[t] = a1; sh2[t] = a2; sh3[t] = a3;
    __syncthreads();
    for (int off = 128; off; off >>= 1) {
        if (t < off) {
            sh0[t] += sh0[t+off]; sh1[t] += sh1[t+off];
            sh2[t] += sh2[t+off]; sh3[t] += sh3[t+off];
        }
        __syncthreads();
    }
    if (t == 0) {
        g_part[blockIdx.x*4 + 0] = sh0[0];
        g_part[blockIdx.x*4 + 1] = sh1[0];
        g_part[blockIdx.x*4 + 2] = sh2[0];
        g_part[blockIdx.x*4 + 3] = sh3[0];
    }
}

// ---------------------------------------------------------------------------
// Reduction stage 2 + final scalar
// ---------------------------------------------------------------------------
__global__ void final_kernel(float* __restrict__ out)
{
    __shared__ double sh[4][256];
    int t = threadIdx.x;
    double a[4] = {0, 0, 0, 0};
    for (int i = t; i < RBLK; i += 256) {
        a[0] += g_part[i*4 + 0];
        a[1] += g_part[i*4 + 1];
        a[2] += g_part[i*4 + 2];
        a[3] += g_part[i*4 + 3];
    }
    for (int k = 0; k < 4; k++) sh[k][t] = a[k];
    __syncthreads();
    for (int off = 128; off; off >>= 1) {
        if (t < off)
            for (int k = 0; k < 4; k++) sh[k][t] += sh[k][t+off];
        __syncthreads();
    }
    if (t == 0) {
        double sum_sp  = sh[0][0];   // sum(skel_pred)
        double sum_spt = sh[1][0];   // sum(skel_pred * target)
        double sum_st  = sh[2][0];   // sum(skel_target)
        double sum_stp = sh[3][0];   // sum(skel_target * pred_prob)
        double tprec = (sum_spt + 1.0) / (sum_sp + 1.0);
        double tsens = (sum_stp + 1.0) / (sum_st + 1.0);
        double cl = 2.0 * tprec * tsens / (tprec + tsens + 1e-7);
        out[0] = (float)(1.0 - cl);
    }
}

// ---------------------------------------------------------------------------
extern "C" void kernel_launch(void* const* d_in, const int* in_sizes, int n_in,
                              void* d_out, int out_size)
{
    const float* pred = (const float*)d_in[0];
    const float* tgt  = (const float*)d_in[1];

    float *prob, *skel, *bufA, *bufB;
    cudaGetSymbolAddress((void**)&prob, g_prob);
    cudaGetSymbolAddress((void**)&skel, g_skel);
    cudaGetSymbolAddress((void**)&bufA, g_bufA);
    cudaGetSymbolAddress((void**)&bufB, g_bufB);

    sigmoid_kernel<<<2048, 256>>>(pred, prob);

    dim3 grid(HW/32, HW/32, BATCH*2);
    dim3 blk(32, 32);

    // pre-loop: skel = relu(img - open(img)); bufA = erode(img)
    skel_iter<<<grid, blk>>>(prob, tgt, skel, bufA, 1);

    // 10 loop iterations: x carried as erode output
    float* cur = bufA;
    float* nxt = bufB;
    for (int it = 0; it < 10; ++it) {
        skel_iter<<<grid, blk>>>(cur, cur + NTOT, skel, nxt, 0);
        float* tmp = cur; cur = nxt; nxt = tmp;
    }

    reduce_kernel<<<RBLK, 256>>>(skel /*skel_pred*/, tgt,
                                 skel + NTOT /*skel_target*/, prob);
    final_kernel<<<1, 256>>>((float*)d_out);
}

// round 4
// speedup vs baseline: 2.6819x; 2.6819x over previous
#include <cuda_runtime.h>

#define HW    512
#define IMG   (HW*HW)          // 262144
#define BATCH 32
#define NTOT  (BATCH*IMG)      // 8388608
#define RBLK  2048

#define TW 128                 // tile width  (output)
#define TH 16                  // tile height (output)
#define SXW 136                // shared row pitch (floats)

// Scratch (__device__ globals; no allocation allowed)
__device__ float  g_prob[NTOT];
__device__ float  g_skel[2*NTOT];
__device__ float  g_bufA[2*NTOT];
__device__ float  g_bufB[2*NTOT];
__device__ double g_part[RBLK*4];

__device__ __forceinline__ int clampi(int v) {
    return v < 0 ? 0 : (v > HW-1 ? HW-1 : v);
}

// ---------------------------------------------------------------------------
__global__ void sigmoid_kernel(const float* __restrict__ in, float* __restrict__ out) {
    int i = blockIdx.x * blockDim.x + threadIdx.x;
    int stride = gridDim.x * blockDim.x;
    const float4* in4 = (const float4*)in;
    float4* out4 = (float4*)out;
    for (; i < NTOT/4; i += stride) {
        float4 v = in4[i];
        v.x = 1.f / (1.f + __expf(-v.x));
        v.y = 1.f / (1.f + __expf(-v.y));
        v.z = 1.f / (1.f + __expf(-v.z));
        v.w = 1.f / (1.f + __expf(-v.w));
        out4[i] = v;
    }
}

// ---------------------------------------------------------------------------
// Fused skeleton iteration on a 128x16 tile:
//   e = cross-min erode(X);  d = 3x3 max dilate(e) (separable);
//   delta = relu(X - d);  skel update;  eout = e (next X).
// Clamp-to-edge == SAME padding with +/-inf identity (idempotent min/max).
// sx is loaded at clamped coords so interior math needs NO clamps; only the
// e-halo ring needs a fix-up copy on image-edge blocks.
//
// Layout (local shared col = global col - bx0 + 4):
//   sx rows 0..19  <-> gy = by0-2 .. by0+17   cols 2..133 <-> gx = bx0-2..bx0+129
//   se rows 0..17  <-> gy = by0-1 .. by0+16   cols 3..132 <-> gx = bx0-1..bx0+128
//   cm rows 0..15  <-> gy = by0   .. by0+15
// ---------------------------------------------------------------------------
__global__ __launch_bounds__(256, 7)
void skel_iter(const float* __restrict__ x0, const float* __restrict__ x1,
               float* __restrict__ skel, float* __restrict__ eout,
               int first, int writeE)
{
    __shared__ float sx[20][SXW];
    __shared__ float se[18][SXW];
    __shared__ float cm[16][SXW];

    const int s = blockIdx.z & 1;
    const int b = blockIdx.z >> 1;
    const float* X  = (s ? x1 : x0) + (size_t)b * IMG;
    float*       SK = skel + (size_t)s * NTOT + (size_t)b * IMG;
    float*       EO = eout + (size_t)s * NTOT + (size_t)b * IMG;

    const int bx0 = blockIdx.x * TW;
    const int by0 = blockIdx.y * TH;
    const int tid = threadIdx.x;

    const bool xL = (bx0 == 0), xR = (bx0 + TW == HW);
    const bool yT = (by0 == 0), yB = (by0 + TH == HW);
    const bool edge = xL | xR | yT | yB;

    // ---- Stage 0: load X tile ----
    if (!edge) {
        // main body: 20 rows x 32 float4, fully in-bounds, no clamps
        #pragma unroll
        for (int i = tid; i < 640; i += 256) {
            int r = i >> 5, c = i & 31;
            float4 v = *(const float4*)&X[(by0 - 2 + r) * HW + bx0 + c * 4];
            *(float4*)&sx[r][4 + c * 4] = v;
        }
        // halo cols: 20 rows x 4 scalars
        for (int i = tid; i < 80; i += 256) {
            int r = i >> 2, h = i & 3;
            int gx = bx0 + ((h < 2) ? h - 2 : TW + h - 2);
            sx[r][(h < 2) ? 2 + h : 130 + h] = X[(by0 - 2 + r) * HW + gx];
        }
    } else {
        #pragma unroll
        for (int i = tid; i < 640; i += 256) {
            int r = i >> 5, c = i & 31;
            int gy = clampi(by0 - 2 + r);          // main cols always in-bounds
            float4 v = *(const float4*)&X[gy * HW + bx0 + c * 4];
            *(float4*)&sx[r][4 + c * 4] = v;
        }
        for (int i = tid; i < 80; i += 256) {
            int r = i >> 2, h = i & 3;
            int gy = clampi(by0 - 2 + r);
            int gx = clampi(bx0 + ((h < 2) ? h - 2 : TW + h - 2));
            sx[r][(h < 2) ? 2 + h : 130 + h] = X[gy * HW + gx];
        }
    }
    __syncthreads();

    // ---- Stage 1: erode (plain offsets; clamped loads already handle
    //       clamp-to-edge for all NON-halo outputs) ----
    // region: 18 rows x 130 cols = 2340 points
    for (int i = tid; i < 2340; i += 256) {
        int r = i / 130;
        int c = i - r * 130 + 3;
        float up = sx[r    ][c];
        float md = sx[r + 1][c];
        float dn = sx[r + 2][c];
        float lf = sx[r + 1][c - 1];
        float rt = sx[r + 1][c + 1];
        float v = fminf(fminf(up, md), dn);
        float h = fminf(fminf(lf, md), rt);
        se[r][c] = fminf(v, h);
    }
    __syncthreads();

    // ---- Stage 1b: halo ring fix-up for image-edge blocks only ----
    if (edge) {
        if (xL) for (int r = tid; r < 18; r += 256) se[r][3]   = se[r][4];
        if (xR) for (int r = tid; r < 18; r += 256) se[r][132] = se[r][131];
        __syncthreads();
        if (yT) for (int c = tid; c < 130; c += 256) se[0][c + 3]  = se[1][c + 3];
        if (yB) for (int c = tid; c < 130; c += 256) se[17][c + 3] = se[16][c + 3];
        __syncthreads();
    }

    // ---- Stage 2: vertical 3-max ----  16 rows x 130 cols = 2080 points
    for (int i = tid; i < 2080; i += 256) {
        int r = i / 130;
        int c = i - r * 130 + 3;
        cm[r][c] = fmaxf(fmaxf(se[r][c], se[r + 1][c]), se[r + 2][c]);
    }
    __syncthreads();

    // ---- Stage 3: horizontal 3-max, delta, skel update, eout ----
    // 16 rows x 32 float4 = 512 items, 2 per thread
    #pragma unroll
    for (int i = tid; i < 512; i += 256) {
        int r  = i >> 5;
        int cb = 4 + ((i & 31) << 2);
        float4 xc = *(float4*)&sx[r + 2][cb];
        float4 ec = *(float4*)&se[r + 1][cb];
        float m0 = cm[r][cb - 1], m1 = cm[r][cb],     m2 = cm[r][cb + 1];
        float m3 = cm[r][cb + 2], m4 = cm[r][cb + 3], m5 = cm[r][cb + 4];
        float d0 = fmaxf(fmaxf(m0, m1), m2);
        float d1 = fmaxf(fmaxf(m1, m2), m3);
        float d2 = fmaxf(fmaxf(m2, m3), m4);
        float d3 = fmaxf(fmaxf(m3, m4), m5);

        float4 dl;
        dl.x = fmaxf(xc.x - d0, 0.f);
        dl.y = fmaxf(xc.y - d1, 0.f);
        dl.z = fmaxf(xc.z - d2, 0.f);
        dl.w = fmaxf(xc.w - d3, 0.f);

        size_t gidx = (size_t)(by0 + r) * HW + bx0 + ((i & 31) << 2);
        if (first) {
            *(float4*)&SK[gidx] = dl;
        } else {
            float4 s0 = *(float4*)&SK[gidx];
            // relu(delta - s*delta) = relu(delta*(1-s))
            s0.x += fmaxf(fmaf(-s0.x, dl.x, dl.x), 0.f);
            s0.y += fmaxf(fmaf(-s0.y, dl.y, dl.y), 0.f);
            s0.z += fmaxf(fmaf(-s0.z, dl.z, dl.z), 0.f);
            s0.w += fmaxf(fmaf(-s0.w, dl.w, dl.w), 0.f);
            *(float4*)&SK[gidx] = s0;
        }
        if (writeE) *(float4*)&EO[gidx] = ec;
    }
}

// ---------------------------------------------------------------------------
__global__ void reduce_kernel(const float* __restrict__ skp, const float* __restrict__ tgt,
                              const float* __restrict__ skt, const float* __restrict__ prob)
{
    __shared__ double sh0[256], sh1[256], sh2[256], sh3[256];
    double a0 = 0, a1 = 0, a2 = 0, a3 = 0;
    int i = blockIdx.x * blockDim.x + threadIdx.x;
    int stride = gridDim.x * blockDim.x;
    const float4* skp4 = (const float4*)skp;
    const float4* tgt4 = (const float4*)tgt;
    const float4* skt4 = (const float4*)skt;
    const float4* prb4 = (const float4*)prob;
    for (; i < NTOT/4; i += stride) {
        float4 sp = skp4[i], tg = tgt4[i], st = skt4[i], pb = prb4[i];
        a0 += (double)sp.x + (double)sp.y + (double)sp.z + (double)sp.w;
        a1 += (double)sp.x*tg.x + (double)sp.y*tg.y + (double)sp.z*tg.z + (double)sp.w*tg.w;
        a2 += (double)st.x + (double)st.y + (double)st.z + (double)st.w;
        a3 += (double)st.x*pb.x + (double)st.y*pb.y + (double)st.z*pb.z + (double)st.w*pb.w;
    }
    int t = threadIdx.x;
    sh0[t] = a0; sh1[t] = a1; sh2[t] = a2; sh3[t] = a3;
    __syncthreads();
    for (int off = 128; off; off >>= 1) {
        if (t < off) {
            sh0[t] += sh0[t+off]; sh1[t] += sh1[t+off];
            sh2[t] += sh2[t+off]; sh3[t] += sh3[t+off];
        }
        __syncthreads();
    }
    if (t == 0) {
        g_part[blockIdx.x*4 + 0] = sh0[0];
        g_part[blockIdx.x*4 + 1] = sh1[0];
        g_part[blockIdx.x*4 + 2] = sh2[0];
        g_part[blockIdx.x*4 + 3] = sh3[0];
    }
}

__global__ void final_kernel(float* __restrict__ out)
{
    __shared__ double sh[4][256];
    int t = threadIdx.x;
    double a[4] = {0, 0, 0, 0};
    for (int i = t; i < RBLK; i += 256) {
        a[0] += g_part[i*4 + 0];
        a[1] += g_part[i*4 + 1];
        a[2] += g_part[i*4 + 2];
        a[3] += g_part[i*4 + 3];
    }
    for (int k = 0; k < 4; k++) sh[k][t] = a[k];
    __syncthreads();
    for (int off = 128; off; off >>= 1) {
        if (t < off)
            for (int k = 0; k < 4; k++) sh[k][t] += sh[k][t+off];
        __syncthreads();
    }
    if (t == 0) {
        double tprec = (sh[1][0] + 1.0) / (sh[0][0] + 1.0);
        double tsens = (sh[3][0] + 1.0) / (sh[2][0] + 1.0);
        double cl = 2.0 * tprec * tsens / (tprec + tsens + 1e-7);
        out[0] = (float)(1.0 - cl);
    }
}

// ---------------------------------------------------------------------------
extern "C" void kernel_launch(void* const* d_in, const int* in_sizes, int n_in,
                              void* d_out, int out_size)
{
    const float* pred = (const float*)d_in[0];
    const float* tgt  = (const float*)d_in[1];

    float *prob, *skel, *bufA, *bufB;
    cudaGetSymbolAddress((void**)&prob, g_prob);
    cudaGetSymbolAddress((void**)&skel, g_skel);
    cudaGetSymbolAddress((void**)&bufA, g_bufA);
    cudaGetSymbolAddress((void**)&bufB, g_bufB);

    sigmoid_kernel<<<2048, 256>>>(pred, prob);

    dim3 grid(HW/TW, HW/TH, BATCH*2);   // (4, 32, 64)
    dim3 blk(256);

    // pre-loop: skel = relu(img - open(img)); bufA = erode(img)
    skel_iter<<<grid, blk>>>(prob, tgt, skel, bufA, 1, 1);

    float* cur = bufA;
    float* nxt = bufB;
    for (int it = 0; it < 10; ++it) {
        int writeE = (it < 9);          // last iteration's erode output unused
        skel_iter<<<grid, blk>>>(cur, cur + NTOT, skel, nxt, 0, writeE);
        float* tmp = cur; cur = nxt; nxt = tmp;
    }

    reduce_kernel<<<RBLK, 256>>>(skel, tgt, skel + NTOT, prob);
    final_kernel<<<1, 256>>>((float*)d_out);
}

// round 5
// speedup vs baseline: 4.1548x; 1.5492x over previous
#include <cuda_runtime.h>
#include <cuda_fp16.h>

#define HW    512
#define IMG   (HW*HW)
#define BATCH 32
#define NTOT  (BATCH*IMG)        // 8388608 px per stream
#define PITCH 144                // shared row pitch in halves
#define NBLK  8192               // 4*32*64 blocks

// __device__ scratch (no allocation allowed)
__device__ __align__(16) __half g_h0[2*NTOT];   // [s][b][y][x]: s0=sigmoid(pred), s1=target
__device__ __align__(16) __half g_eA[2*NTOT];
__device__ __align__(16) __half g_eB[2*NTOT];
__device__ __align__(16) float  g_P [2*NTOT];   // running product (1-skel)
__device__ double g_part[NBLK*2];

__device__ __forceinline__ int clampi(int v) {
    return v < 0 ? 0 : (v > HW-1 ? HW-1 : v);
}

// ---- 4-half vector helpers ------------------------------------------------
struct H4 { __half2 a, b; };

__device__ __forceinline__ H4 ld4(const __half* p) {
    uint2 v = *(const uint2*)p;
    H4 h;
    h.a = *reinterpret_cast<__half2*>(&v.x);
    h.b = *reinterpret_cast<__half2*>(&v.y);
    return h;
}
__device__ __forceinline__ void st4(__half* p, H4 h) {
    uint2 v;
    v.x = *reinterpret_cast<unsigned*>(&h.a);
    v.y = *reinterpret_cast<unsigned*>(&h.b);
    *(uint2*)p = v;
}

// erode = min(vert3, horiz3), both windows include center
__device__ __forceinline__ H4 erode4(H4 up, H4 md, H4 dn, __half pl, __half nr) {
    __half2 v0 = __hmin2(__hmin2(up.a, md.a), dn.a);
    __half2 v1 = __hmin2(__hmin2(up.b, md.b), dn.b);
    __half2 sl0 = __halves2half2(pl, __low2half(md.a));
    __half2 sr0 = __halves2half2(__high2half(md.a), __low2half(md.b));
    __half2 sr1 = __halves2half2(__high2half(md.b), nr);
    __half2 h0 = __hmin2(__hmin2(sl0, md.a), sr0);
    __half2 h1 = __hmin2(__hmin2(sr0, md.b), sr1);
    H4 e; e.a = __hmin2(v0, h0); e.b = __hmin2(v1, h1); return e;
}

__device__ __forceinline__ H4 hmax34(H4 c, __half pl, __half nr) {
    __half2 sl0 = __halves2half2(pl, __low2half(c.a));
    __half2 sr0 = __halves2half2(__high2half(c.a), __low2half(c.b));
    __half2 sr1 = __halves2half2(__high2half(c.b), nr);
    H4 d;
    d.a = __hmax2(__hmax2(sl0, c.a), sr0);
    d.b = __hmax2(__hmax2(sr0, c.b), sr1);
    return d;
}

__device__ __forceinline__ H4 vmax4(H4 x, H4 y, H4 z) {
    H4 r;
    r.a = __hmax2(__hmax2(x.a, y.a), z.a);
    r.b = __hmax2(__hmax2(x.b, y.b), z.b);
    return r;
}

// ---------------------------------------------------------------------------
// prep: h0[s=0] = half(sigmoid(pred)), h0[s=1] = half(target)
// ---------------------------------------------------------------------------
__global__ void prep_kernel(const float* __restrict__ pred, const float* __restrict__ tgt) {
    int i = blockIdx.x * blockDim.x + threadIdx.x;
    int stride = gridDim.x * blockDim.x;
    const float4* p4 = (const float4*)pred;
    const float4* t4 = (const float4*)tgt;
    for (; i < NTOT/4; i += stride) {
        float4 p = p4[i];
        p.x = 1.f/(1.f+__expf(-p.x)); p.y = 1.f/(1.f+__expf(-p.y));
        p.z = 1.f/(1.f+__expf(-p.z)); p.w = 1.f/(1.f+__expf(-p.w));
        H4 hp; hp.a = __floats2half2_rn(p.x, p.y); hp.b = __floats2half2_rn(p.z, p.w);
        st4(&g_h0[(size_t)4*i], hp);
        float4 t = t4[i];
        H4 ht; ht.a = __floats2half2_rn(t.x, t.y); ht.b = __floats2half2_rn(t.z, t.w);
        st4(&g_h0[(size_t)NTOT + 4*i], ht);
    }
}

// ---------------------------------------------------------------------------
// pair_iter: two fused skeleton stages.
//   e1 = erode(X); delta_a = relu(X - dilate(e1))
//   e2 = erode(e1); delta_b = relu(e1 - dilate(e2))
//   P  = (first ? 1 : P) * (1-delta_a)*(1-delta_b);  Eout = e2
// Half-col mapping: h = gx - bx0 + 8. X tile rows i: gy=by0-3+i (22 rows),
// written h in [5,138]. e1 rows rr: gy=by0-2+rr (20). vm1 rows r: gy=by0+r.
// e2 rows m: gy=by0-1+m (18). Clamp-to-edge == SAME pad (idempotent min/max);
// out-of-image halo rings of e1/e2 fixed by copy on edge blocks.
// ---------------------------------------------------------------------------
__global__ __launch_bounds__(256)
void pair_iter(const __half* __restrict__ Xin, float* __restrict__ P,
               __half* __restrict__ Eout, int first)
{
    __shared__ __half sx [22*PITCH];   // X, later vm2 (16 rows)
    __shared__ __half se1[20*PITCH];   // e1
    __shared__ __half sb [18*PITCH];   // vm1 (16 rows), later e2 (18 rows)

    const int s = blockIdx.z & 1;
    const int b = blockIdx.z >> 1;
    const __half* X  = Xin  + (size_t)s*NTOT + (size_t)b*IMG;
    float*        Pp = P    + (size_t)s*NTOT + (size_t)b*IMG;
    __half*       EO = Eout + (size_t)s*NTOT + (size_t)b*IMG;

    const int bx0 = blockIdx.x * 128;
    const int by0 = blockIdx.y * 16;
    const int tid = threadIdx.x;

    const bool xL = (bx0 == 0), xR = (bx0 + 128 == HW);
    const bool yT = (by0 == 0), yB = (by0 + 16 == HW);
    const bool edge = xL | xR | yT | yB;

    // ---- load X tile (22 rows) ----
    if (!edge) {
        for (int i = tid; i < 704; i += 256) {           // main: 22 x 32 uint2
            int r = i >> 5, c = i & 31;
            uint2 v = *(const uint2*)(X + (by0-3+r)*HW + bx0 + 4*c);
            *(uint2*)(sx + r*PITCH + 8 + 4*c) = v;
        }
        for (int i = tid; i < 132; i += 256) {           // halo: 22 x 6 halves
            int r = i / 6, h = i - 6*r;
            int hh = (h < 3) ? 5 + h : 133 + h;          // 5,6,7 / 136,137,138
            sx[r*PITCH + hh] = X[(by0-3+r)*HW + bx0 + hh - 8];
        }
    } else {
        for (int i = tid; i < 704; i += 256) {
            int r = i >> 5, c = i & 31;
            int gy = clampi(by0 - 3 + r);
            uint2 v = *(const uint2*)(X + gy*HW + bx0 + 4*c);
            *(uint2*)(sx + r*PITCH + 8 + 4*c) = v;
        }
        for (int i = tid; i < 132; i += 256) {
            int r = i / 6, h = i - 6*r;
            int hh = (h < 3) ? 5 + h : 133 + h;
            int gy = clampi(by0 - 3 + r);
            int gx = clampi(bx0 + hh - 8);
            sx[r*PITCH + hh] = X[gy*HW + gx];
        }
    }
    __syncthreads();

    // ---- e1 = erode(X): 20 rows x 34 units ----
    for (int i = tid; i < 680; i += 256) {
        int rr = i / 34;
        int j  = i - 34*rr + 1;
        const __half* m = sx + (rr+1)*PITCH + 4*j;
        H4 e = erode4(ld4(sx + rr*PITCH + 4*j), ld4(m), ld4(sx + (rr+2)*PITCH + 4*j),
                      m[-1], m[4]);
        st4(se1 + rr*PITCH + 4*j, e);
    }
    __syncthreads();

    // ---- e1 ring fix (edge blocks only) ----
    if (edge) {
        if (xL) for (int rr = tid; rr < 20; rr += 256) {
            __half v = se1[rr*PITCH + 8]; se1[rr*PITCH + 6] = v; se1[rr*PITCH + 7] = v;
        }
        if (xR) for (int rr = tid; rr < 20; rr += 256) {
            __half v = se1[rr*PITCH + 135]; se1[rr*PITCH + 136] = v; se1[rr*PITCH + 137] = v;
        }
        __syncthreads();
        if (yT) for (int i = tid; i < 68; i += 256) {
            int row = i / 34, j = i - 34*row + 1;
            *(uint2*)(se1 + row*PITCH + 4*j) = *(uint2*)(se1 + 2*PITCH + 4*j);
        }
        if (yB) for (int i = tid; i < 68; i += 256) {
            int row = 18 + i / 34, j = i % 34 + 1;
            *(uint2*)(se1 + row*PITCH + 4*j) = *(uint2*)(se1 + 17*PITCH + 4*j);
        }
        __syncthreads();
    }

    // ---- vm1 = vertical 3-max of e1: 16 rows x 34 units (into sb) ----
    for (int i = tid; i < 544; i += 256) {
        int r = i / 34;
        int j = i - 34*r + 1;
        H4 v = vmax4(ld4(se1 + (r+1)*PITCH + 4*j), ld4(se1 + (r+2)*PITCH + 4*j),
                     ld4(se1 + (r+3)*PITCH + 4*j));
        st4(sb + r*PITCH + 4*j, v);
    }
    __syncthreads();

    // ---- delta_a -> pm registers ----
    float pm[2][4];
    #pragma unroll
    for (int it = 0; it < 2; ++it) {
        int i = tid + 256*it;
        int r = i >> 5, u = i & 31, j = u + 2;
        const __half* vp = sb + r*PITCH + 4*j;
        H4 d  = hmax34(ld4(vp), vp[-1], vp[4]);
        H4 xc = ld4(sx + (r+3)*PITCH + 4*j);
        float2 x0 = __half22float2(xc.a), x1 = __half22float2(xc.b);
        float2 d0 = __half22float2(d.a),  d1 = __half22float2(d.b);
        pm[it][0] = 1.f - fmaxf(x0.x - d0.x, 0.f);
        pm[it][1] = 1.f - fmaxf(x0.y - d0.y, 0.f);
        pm[it][2] = 1.f - fmaxf(x1.x - d1.x, 0.f);
        pm[it][3] = 1.f - fmaxf(x1.y - d1.y, 0.f);
    }
    __syncthreads();   // all vm1 reads done before sb is overwritten by e2

    // ---- e2 = erode(e1): 18 rows x 34 units (into sb) ----
    for (int i = tid; i < 612; i += 256) {
        int m = i / 34;
        int j = i - 34*m + 1;
        const __half* md = se1 + (m+1)*PITCH + 4*j;
        H4 e = erode4(ld4(se1 + m*PITCH + 4*j), ld4(md), ld4(se1 + (m+2)*PITCH + 4*j),
                      md[-1], md[4]);
        st4(sb + m*PITCH + 4*j, e);
    }
    __syncthreads();

    // ---- e2 ring fix ----
    if (edge) {
        if (xL) for (int m = tid; m < 18; m += 256) sb[m*PITCH + 7]   = sb[m*PITCH + 8];
        if (xR) for (int m = tid; m < 18; m += 256) sb[m*PITCH + 136] = sb[m*PITCH + 135];
        __syncthreads();
        if (yT) for (int i = tid; i < 34; i += 256) {
            int j = i + 1;
            *(uint2*)(sb + 4*j) = *(uint2*)(sb + PITCH + 4*j);
        }
        if (yB) for (int i = tid; i < 34; i += 256) {
            int j = i + 1;
            *(uint2*)(sb + 17*PITCH + 4*j) = *(uint2*)(sb + 16*PITCH + 4*j);
        }
        __syncthreads();
    }

    // ---- vm2 = vertical 3-max of e2: into sx (X is dead) ----
    for (int i = tid; i < 544; i += 256) {
        int r = i / 34;
        int j = i - 34*r + 1;
        H4 v = vmax4(ld4(sb + r*PITCH + 4*j), ld4(sb + (r+1)*PITCH + 4*j),
                     ld4(sb + (r+2)*PITCH + 4*j));
        st4(sx + r*PITCH + 4*j, v);
    }
    __syncthreads();

    // ---- delta_b, P update, Eout ----
    #pragma unroll
    for (int it = 0; it < 2; ++it) {
        int i = tid + 256*it;
        int r = i >> 5, u = i & 31, j = u + 2;
        const __half* vp = sx + r*PITCH + 4*j;
        H4 d   = hmax34(ld4(vp), vp[-1], vp[4]);
        H4 e1c = ld4(se1 + (r+2)*PITCH + 4*j);
        float2 x0 = __half22float2(e1c.a), x1 = __half22float2(e1c.b);
        float2 d0 = __half22float2(d.a),   d1 = __half22float2(d.b);
        float4 pv;
        pv.x = pm[it][0] * (1.f - fmaxf(x0.x - d0.x, 0.f));
        pv.y = pm[it][1] * (1.f - fmaxf(x0.y - d0.y, 0.f));
        pv.z = pm[it][2] * (1.f - fmaxf(x1.x - d1.x, 0.f));
        pv.w = pm[it][3] * (1.f - fmaxf(x1.y - d1.y, 0.f));

        int gidx = (by0 + r)*HW + bx0 + 4*u;
        if (!first) {
            float4 o = *(const float4*)(Pp + gidx);
            pv.x *= o.x; pv.y *= o.y; pv.z *= o.z; pv.w *= o.w;
        }
        *(float4*)(Pp + gidx) = pv;
        *(uint2*)(EO + gidx) = *(const uint2*)(sb + (r+1)*PITCH + 4*j);
    }
}

// ---------------------------------------------------------------------------
// final_iter: last stage (delta_10) + skel + in-kernel reduction.
//   skel = 1 - P*(1-delta); a0 = sum(skel); a1 = sum(skel * other-stream-h0)
// X rows i: gy=by0-2+i (20, written h [6,137]); e rows m: gy=by0-1+m (18);
// vm rows r: gy=by0+r.
// ---------------------------------------------------------------------------
__global__ __launch_bounds__(256)
void final_iter(const __half* __restrict__ Xin, const float* __restrict__ P,
                const __half* __restrict__ H0)
{
    __shared__ __half sx[20*PITCH];
    __shared__ __half se[18*PITCH];
    __shared__ __half vm[16*PITCH];
    __shared__ double sred[512];

    const int s = blockIdx.z & 1;
    const int b = blockIdx.z >> 1;
    const __half* X   = Xin + (size_t)s*NTOT + (size_t)b*IMG;
    const float*  Pp  = P   + (size_t)s*NTOT + (size_t)b*IMG;
    const __half* OTH = H0  + (size_t)(1-s)*NTOT + (size_t)b*IMG;

    const int bx0 = blockIdx.x * 128;
    const int by0 = blockIdx.y * 16;
    const int tid = threadIdx.x;

    const bool xL = (bx0 == 0), xR = (bx0 + 128 == HW);
    const bool yT = (by0 == 0), yB = (by0 + 16 == HW);
    const bool edge = xL | xR | yT | yB;

    if (!edge) {
        for (int i = tid; i < 640; i += 256) {
            int r = i >> 5, c = i & 31;
            *(uint2*)(sx + r*PITCH + 8 + 4*c) =
                *(const uint2*)(X + (by0-2+r)*HW + bx0 + 4*c);
        }
        for (int i = tid; i < 80; i += 256) {
            int r = i >> 2, h = i & 3;
            int hh = (h < 2) ? 6 + h : 134 + h;          // 6,7 / 136,137
            sx[r*PITCH + hh] = X[(by0-2+r)*HW + bx0 + hh - 8];
        }
    } else {
        for (int i = tid; i < 640; i += 256) {
            int r = i >> 5, c = i & 31;
            int gy = clampi(by0 - 2 + r);
            *(uint2*)(sx + r*PITCH + 8 + 4*c) = *(const uint2*)(X + gy*HW + bx0 + 4*c);
        }
        for (int i = tid; i < 80; i += 256) {
            int r = i >> 2, h = i & 3;
            int hh = (h < 2) ? 6 + h : 134 + h;
            int gy = clampi(by0 - 2 + r);
            int gx = clampi(bx0 + hh - 8);
            sx[r*PITCH + hh] = X[gy*HW + gx];
        }
    }
    __syncthreads();

    for (int i = tid; i < 612; i += 256) {      // e = erode(X): 18 x 34
        int m = i / 34;
        int j = i - 34*m + 1;
        const __half* md = sx + (m+1)*PITCH + 4*j;
        H4 e = erode4(ld4(sx + m*PITCH + 4*j), ld4(md), ld4(sx + (m+2)*PITCH + 4*j),
                      md[-1], md[4]);
        st4(se + m*PITCH + 4*j, e);
    }
    __syncthreads();

    if (edge) {
        if (xL) for (int m = tid; m < 18; m += 256) se[m*PITCH + 7]   = se[m*PITCH + 8];
        if (xR) for (int m = tid; m < 18; m += 256) se[m*PITCH + 136] = se[m*PITCH + 135];
        __syncthreads();
        if (yT) for (int i = tid; i < 34; i += 256) {
            int j = i + 1;
            *(uint2*)(se + 4*j) = *(uint2*)(se + PITCH + 4*j);
        }
        if (yB) for (int i = tid; i < 34; i += 256) {
            int j = i + 1;
            *(uint2*)(se + 17*PITCH + 4*j) = *(uint2*)(se + 16*PITCH + 4*j);
        }
        __syncthreads();
    }

    for (int i = tid; i < 544; i += 256) {      // vertical 3-max
        int r = i / 34;
        int j = i - 34*r + 1;
        H4 v = vmax4(ld4(se + r*PITCH + 4*j), ld4(se + (r+1)*PITCH + 4*j),
                     ld4(se + (r+2)*PITCH + 4*j));
        st4(vm + r*PITCH + 4*j, v);
    }
    __syncthreads();

    double a0 = 0.0, a1 = 0.0;
    #pragma unroll
    for (int it = 0; it < 2; ++it) {
        int i = tid + 256*it;
        int r = i >> 5, u = i & 31, j = u + 2;
        const __half* vp = vm + r*PITCH + 4*j;
        H4 d  = hmax34(ld4(vp), vp[-1], vp[4]);
        H4 xc = ld4(sx + (r+2)*PITCH + 4*j);
        float2 x0 = __half22float2(xc.a), x1 = __half22float2(xc.b);
        float2 d0 = __half22float2(d.a),  d1 = __half22float2(d.b);
        int gidx = (by0 + r)*HW + bx0 + 4*u;
        float4 Po = *(const float4*)(Pp + gidx);
        float sk0 = 1.f - Po.x * (1.f - fmaxf(x0.x - d0.x, 0.f));
        float sk1 = 1.f - Po.y * (1.f - fmaxf(x0.y - d0.y, 0.f));
        float sk2 = 1.f - Po.z * (1.f - fmaxf(x1.x - d1.x, 0.f));
        float sk3 = 1.f - Po.w * (1.f - fmaxf(x1.y - d1.y, 0.f));
        H4 ov = ld4(OTH + gidx);
        float2 o0 = __half22float2(ov.a), o1 = __half22float2(ov.b);
        a0 += (double)sk0 + (double)sk1 + (double)sk2 + (double)sk3;
        a1 += (double)sk0*o0.x + (double)sk1*o0.y + (double)sk2*o1.x + (double)sk3*o1.y;
    }

    sred[tid] = a0; sred[256 + tid] = a1;
    __syncthreads();
    for (int off = 128; off; off >>= 1) {
        if (tid < off) {
            sred[tid] += sred[tid + off];
            sred[256 + tid] += sred[256 + tid + off];
        }
        __syncthreads();
    }
    if (tid == 0) {
        int bid = blockIdx.x + gridDim.x * (blockIdx.y + gridDim.y * blockIdx.z);
        g_part[bid*2 + 0] = sred[0];
        g_part[bid*2 + 1] = sred[256];
    }
}

// ---------------------------------------------------------------------------
__global__ void final_sum(float* __restrict__ out)
{
    __shared__ double sh[4][256];
    int t = threadIdx.x;
    double a[4] = {0, 0, 0, 0};
    for (int i = t; i < NBLK; i += 256) {
        int s = (i >> 7) & 1;                 // bid = x + 4y + 128z, s = z&1
        a[2*s + 0] += g_part[i*2 + 0];
        a[2*s + 1] += g_part[i*2 + 1];
    }
    for (int k = 0; k < 4; k++) sh[k][t] = a[k];
    __syncthreads();
    for (int off = 128; off; off >>= 1) {
        if (t < off)
            for (int k = 0; k < 4; k++) sh[k][t] += sh[k][t + off];
        __syncthreads();
    }
    if (t == 0) {
        // s=0: skel_pred sums (a0=sum skel, a1=sum skel*target)
        // s=1: skel_target sums (a2=sum skel, a3=sum skel*prob)
        double tprec = (sh[1][0] + 1.0) / (sh[0][0] + 1.0);
        double tsens = (sh[3][0] + 1.0) / (sh[2][0] + 1.0);
        double cl = 2.0 * tprec * tsens / (tprec + tsens + 1e-7);
        out[0] = (float)(1.0 - cl);
    }
}

// ---------------------------------------------------------------------------
extern "C" void kernel_launch(void* const* d_in, const int* in_sizes, int n_in,
                              void* d_out, int out_size)
{
    const float* pred = (const float*)d_in[0];
    const float* tgt  = (const float*)d_in[1];

    __half *h0, *eA, *eB;
    float  *P;
    cudaGetSymbolAddress((void**)&h0, g_h0);
    cudaGetSymbolAddress((void**)&eA, g_eA);
    cudaGetSymbolAddress((void**)&eB, g_eB);
    cudaGetSymbolAddress((void**)&P,  g_P);

    prep_kernel<<<2048, 256>>>(pred, tgt);

    dim3 grid(HW/128, HW/16, BATCH*2);   // (4, 32, 64)
    dim3 blk(256);

    // stages 0..10: deltas delta_0..delta_10; e-chain e0=h0 -> e2 -> ... -> e10
    pair_iter<<<grid, blk>>>(h0, P, eA, 1);   // delta0, delta1; out e2
    pair_iter<<<grid, blk>>>(eA, P, eB, 0);   // delta2, delta3; out e4
    pair_iter<<<grid, blk>>>(eB, P, eA, 0);   // delta4, delta5; out e6
    pair_iter<<<grid, blk>>>(eA, P, eB, 0);   // delta6, delta7; out e8
    pair_iter<<<grid, blk>>>(eB, P, eA, 0);   // delta8, delta9; out e10
    final_iter<<<grid, blk>>>(eA, P, h0);     // delta10 + skel + reduction
    final_sum<<<1, 256>>>((float*)d_out);
}

// round 7
// speedup vs baseline: 6.5182x; 1.5688x over previous
#include <cuda_runtime.h>
#include <cuda_fp16.h>

#define HW    512
#define IMG   (HW*HW)
#define BATCH 32
#define NTOT  (BATCH*IMG)        // per stream
#define NWARP 2048               // 64 images * 32 stripes
#define FULLM 0xffffffffu

// __device__ scratch (no allocation allowed)
__device__ __align__(16) __half g_h0[2*NTOT];   // image i = s*32+b
__device__ __align__(16) __half g_eA[2*NTOT];
__device__ __align__(16) __half g_eB[2*NTOT];
__device__ __align__(16) float  g_P [2*NTOT];
__device__ double g_part[NWARP*2];

__device__ __forceinline__ int clampi(int v){ return v<0?0:(v>HW-1?HW-1:v); }

struct Row { __half2 h[8]; };    // 16 halves: lane covers gx [16*lane, 16*lane+15]

__device__ __forceinline__ unsigned h2u(__half2 x){ return *reinterpret_cast<unsigned*>(&x); }
__device__ __forceinline__ __half2  u2h(unsigned x){ return *reinterpret_cast<__half2*>(&x); }

__device__ __forceinline__ Row ld_row(const __half* base, int y, int xoff){
    const uint4* p = reinterpret_cast<const uint4*>(base + (size_t)clampi(y)*HW + xoff);
    uint4 a = p[0], b = p[1];
    Row r;
    r.h[0]=u2h(a.x); r.h[1]=u2h(a.y); r.h[2]=u2h(a.z); r.h[3]=u2h(a.w);
    r.h[4]=u2h(b.x); r.h[5]=u2h(b.y); r.h[6]=u2h(b.z); r.h[7]=u2h(b.w);
    return r;
}
__device__ __forceinline__ void st_row(__half* base, int y, int xoff, const Row& r){
    uint4 a, b;
    a.x=h2u(r.h[0]); a.y=h2u(r.h[1]); a.z=h2u(r.h[2]); a.w=h2u(r.h[3]);
    b.x=h2u(r.h[4]); b.y=h2u(r.h[5]); b.z=h2u(r.h[6]); b.w=h2u(r.h[7]);
    uint4* p = reinterpret_cast<uint4*>(base + (size_t)y*HW + xoff);
    p[0]=a; p[1]=b;
}

// horizontal 3-min over the 512-wide row; lane-boundary halves via shuffle;
// image x-edges use duplicated edge element (== SAME pad identity for min).
__device__ __forceinline__ Row hmin3_row(const Row& m, int lane){
    unsigned up = __shfl_up_sync(FULLM, h2u(m.h[7]), 1);
    unsigned dn = __shfl_down_sync(FULLM, h2u(m.h[0]), 1);
    __half L = (lane==0)  ? __low2half(m.h[0])  : __high2half(u2h(up));
    __half R = (lane==31) ? __high2half(m.h[7]) : __low2half(u2h(dn));
    Row o;
    #pragma unroll
    for (int i=0;i<8;i++){
        __half a = (i==0)? L : __high2half(m.h[i-1]);
        __half b = (i==7)? R : __low2half(m.h[i+1]);
        __half2 sl = __halves2half2(a, __low2half(m.h[i]));
        __half2 sr = __halves2half2(__high2half(m.h[i]), b);
        o.h[i] = __hmin2(__hmin2(sl, m.h[i]), sr);
    }
    return o;
}
__device__ __forceinline__ Row hmax3_row(const Row& m, int lane){
    unsigned up = __shfl_up_sync(FULLM, h2u(m.h[7]), 1);
    unsigned dn = __shfl_down_sync(FULLM, h2u(m.h[0]), 1);
    __half L = (lane==0)  ? __low2half(m.h[0])  : __high2half(u2h(up));
    __half R = (lane==31) ? __high2half(m.h[7]) : __low2half(u2h(dn));
    Row o;
    #pragma unroll
    for (int i=0;i<8;i++){
        __half a = (i==0)? L : __high2half(m.h[i-1]);
        __half b = (i==7)? R : __low2half(m.h[i+1]);
        __half2 sl = __halves2half2(a, __low2half(m.h[i]));
        __half2 sr = __halves2half2(__high2half(m.h[i]), b);
        o.h[i] = __hmax2(__hmax2(sl, m.h[i]), sr);
    }
    return o;
}

// erode = min(vert 3-min, horiz 3-min) (both windows include center)
__device__ __forceinline__ Row erode_row(const Row& up, const Row& md, const Row& dn, int lane){
    Row h = hmin3_row(md, lane);
    Row o;
    #pragma unroll
    for (int i=0;i<8;i++)
        o.h[i] = __hmin2(__hmin2(__hmin2(up.h[i], md.h[i]), dn.h[i]), h.h[i]);
    return o;
}
// dilate = 3x3 max, separable
__device__ __forceinline__ Row dilate_rows(const Row& a, const Row& b, const Row& c, int lane){
    Row v;
    #pragma unroll
    for (int i=0;i<8;i++) v.h[i] = __hmax2(__hmax2(a.h[i], b.h[i]), c.h[i]);
    return hmax3_row(v, lane);
}

// ---------------------------------------------------------------------------
__global__ void prep_kernel(const float* __restrict__ pred, const float* __restrict__ tgt) {
    int i = blockIdx.x * blockDim.x + threadIdx.x;
    int stride = gridDim.x * blockDim.x;
    const float4* p4 = (const float4*)pred;
    const float4* t4 = (const float4*)tgt;
    for (; i < NTOT/4; i += stride) {
        float4 p = p4[i];
        p.x = 1.f/(1.f+__expf(-p.x)); p.y = 1.f/(1.f+__expf(-p.y));
        p.z = 1.f/(1.f+__expf(-p.z)); p.w = 1.f/(1.f+__expf(-p.w));
        uint2 hp;
        hp.x = h2u(__floats2half2_rn(p.x, p.y));
        hp.y = h2u(__floats2half2_rn(p.z, p.w));
        *(uint2*)&g_h0[(size_t)4*i] = hp;
        float4 t = t4[i];
        uint2 ht;
        ht.x = h2u(__floats2half2_rn(t.x, t.y));
        ht.y = h2u(__floats2half2_rn(t.z, t.w));
        *(uint2*)&g_h0[(size_t)NTOT + 4*i] = ht;
    }
}

// ---------------------------------------------------------------------------
// pair_iter: two fused skeleton stages, register rolling pipeline.
// One warp sweeps a 16-row stripe of one image (full 512-px width).
//   e1 = erode(X); delta_a = relu(X - dilate(e1))
//   e2 = erode(e1); delta_b = relu(e1 - dilate(e2))
//   P[y] = (first ? 1 : P[y]) * (1-delta_a)*(1-delta_b);  Eout[y] = e2[y]
// Vertical clamp at image top/bottom is done at the VALUE level (duplicate the
// edge row of each chain quantity), which is exactly SAME padding semantics.
// ---------------------------------------------------------------------------
__global__ void __launch_bounds__(128)
pair_iter(const __half* __restrict__ Xin, float* __restrict__ P,
          __half* __restrict__ Eout, int first)
{
    const int w     = blockIdx.x * 4 + (threadIdx.x >> 5);
    const int lane  = threadIdx.x & 31;
    const int image = w >> 5;              // 0..63
    const int y0    = (w & 31) << 4;       // stripe start row
    const int xoff  = lane * 16;

    const __half* ptrX = Xin + (size_t)image * IMG;
    float*        ptrP = P   + (size_t)image * IMG;
    __half*       ptrE = Eout+ (size_t)image * IMG;

    // ---- prologue ----
    Row x_m3 = ld_row(ptrX, y0-3, xoff);
    Row x_m2 = ld_row(ptrX, y0-2, xoff);
    Row x_m1 = ld_row(ptrX, y0-1, xoff);
    Row x_0  = ld_row(ptrX, y0  , xoff);
    Row x_p1 = ld_row(ptrX, y0+1, xoff);
    Row x_p2 = ld_row(ptrX, y0+2, xoff);

    Row e1_0  = erode_row(x_m1, x_0, x_p1, lane);       // e1@y0
    Row e1_p1 = erode_row(x_0, x_p1, x_p2, lane);       // e1@y0+1
    Row e1_m1, e1_m2;
    if (y0 == 0) { e1_m1 = e1_0; e1_m2 = e1_0; }
    else {
        e1_m1 = erode_row(x_m2, x_m1, x_0, lane);       // e1@y0-1
        e1_m2 = erode_row(x_m3, x_m2, x_m1, lane);      // e1@y0-2
    }
    Row e2_0 = erode_row(e1_m1, e1_0, e1_p1, lane);     // e2@y0
    Row e2_m1;
    if (y0 == 0) e2_m1 = e2_0;
    else         e2_m1 = erode_row(e1_m2, e1_m1, e1_0, lane);  // e2@y0-1

    Row XA = x_0, XB = x_p1, XC = x_p2;   // X@y, X@y+1, X@y+2

    #pragma unroll 4
    for (int k = 0; k < 16; ++k) {
        const int y = y0 + k;
        Row Xn = ld_row(ptrX, y+3, xoff);
        Row e1n, e2n;
        if (y+2 <= HW-1) e1n = erode_row(XB, XC, Xn, lane);        else e1n = e1_p1;
        if (y+1 <= HW-1) e2n = erode_row(e1_0, e1_p1, e1n, lane);  else e2n = e2_0;

        Row d1 = dilate_rows(e1_m1, e1_0, e1_p1, lane);
        Row d2 = dilate_rows(e2_m1, e2_0, e2n, lane);

        float* Prow = ptrP + (size_t)y * HW + xoff;
        #pragma unroll
        for (int i = 0; i < 8; i += 2) {
            float2 xa=__half22float2(XA.h[i]),   xb=__half22float2(XA.h[i+1]);
            float2 da=__half22float2(d1.h[i]),   db=__half22float2(d1.h[i+1]);
            float2 ea=__half22float2(e1_0.h[i]), eb=__half22float2(e1_0.h[i+1]);
            float2 ga=__half22float2(d2.h[i]),   gb=__half22float2(d2.h[i+1]);
            float4 pv;
            pv.x = (1.f - fmaxf(xa.x-da.x, 0.f)) * (1.f - fmaxf(ea.x-ga.x, 0.f));
            pv.y = (1.f - fmaxf(xa.y-da.y, 0.f)) * (1.f - fmaxf(ea.y-ga.y, 0.f));
            pv.z = (1.f - fmaxf(xb.x-db.x, 0.f)) * (1.f - fmaxf(eb.x-gb.x, 0.f));
            pv.w = (1.f - fmaxf(xb.y-db.y, 0.f)) * (1.f - fmaxf(eb.y-gb.y, 0.f));
            float4* pp = (float4*)(Prow + 2*i);
            if (!first) {
                float4 o = *pp;
                pv.x *= o.x; pv.y *= o.y; pv.z *= o.z; pv.w *= o.w;
            }
            *pp = pv;
        }
        st_row(ptrE, y, xoff, e2_0);

        // rotate windows
        XA = XB; XB = XC; XC = Xn;
        e1_m1 = e1_0; e1_0 = e1_p1; e1_p1 = e1n;
        e2_m1 = e2_0; e2_0 = e2n;
    }
}

// ---------------------------------------------------------------------------
// final_iter: last stage (delta_10) + skel + per-warp reduction.
//   skel[y] = 1 - P[y]*(1 - relu(X[y]-dilate(erode(X))[y]))
//   a0 = sum(skel); a1 = sum(skel * other-stream h0)
// ---------------------------------------------------------------------------
__global__ void __launch_bounds__(128)
final_iter(const __half* __restrict__ Xin, const float* __restrict__ P,
           const __half* __restrict__ H0)
{
    const int w     = blockIdx.x * 4 + (threadIdx.x >> 5);
    const int lane  = threadIdx.x & 31;
    const int image = w >> 5;
    const int y0    = (w & 31) << 4;
    const int xoff  = lane * 16;

    const __half* ptrX = Xin + (size_t)image * IMG;
    const float*  ptrP = P   + (size_t)image * IMG;
    const __half* ptrO = H0  + (size_t)(image ^ 32) * IMG;   // opposite stream

    Row XA = ld_row(ptrX, y0,   xoff);       // X@y
    Row XB = ld_row(ptrX, y0+1, xoff);       // X@y+1
    Row x_m1 = ld_row(ptrX, y0-1, xoff);
    Row x_m2 = ld_row(ptrX, y0-2, xoff);

    Row e_0 = erode_row(x_m1, XA, XB, lane);             // e@y0
    Row e_m1;
    if (y0 == 0) e_m1 = e_0;
    else         e_m1 = erode_row(x_m2, x_m1, XA, lane); // e@y0-1

    double a0 = 0.0, a1 = 0.0;

    #pragma unroll 4
    for (int k = 0; k < 16; ++k) {
        const int y = y0 + k;
        Row Xn = ld_row(ptrX, y+2, xoff);
        Row e_p1;
        if (y+1 <= HW-1) e_p1 = erode_row(XA, XB, Xn, lane); else e_p1 = e_0;
        Row d = dilate_rows(e_m1, e_0, e_p1, lane);

        const float* Prow = ptrP + (size_t)y * HW + xoff;
        const uint4* op   = reinterpret_cast<const uint4*>(ptrO + (size_t)y * HW + xoff);
        uint4 oa = op[0], ob = op[1];
        const unsigned ou[8] = {oa.x, oa.y, oa.z, oa.w, ob.x, ob.y, ob.z, ob.w};

        float s0 = 0.f, s1 = 0.f;
        #pragma unroll
        for (int i = 0; i < 8; i += 2) {
            float2 xa=__half22float2(XA.h[i]), xb=__half22float2(XA.h[i+1]);
            float2 da=__half22float2(d.h[i]),  db=__half22float2(d.h[i+1]);
            float4 Po = *(const float4*)(Prow + 2*i);
            float sk0 = 1.f - Po.x * (1.f - fmaxf(xa.x-da.x, 0.f));
            float sk1 = 1.f - Po.y * (1.f - fmaxf(xa.y-da.y, 0.f));
            float sk2 = 1.f - Po.z * (1.f - fmaxf(xb.x-db.x, 0.f));
            float sk3 = 1.f - Po.w * (1.f - fmaxf(xb.y-db.y, 0.f));
            float2 o0 = __half22float2(u2h(ou[i]));
            float2 o1 = __half22float2(u2h(ou[i+1]));
            s0 += (sk0 + sk1) + (sk2 + sk3);
            s1 += (sk0*o0.x + sk1*o0.y) + (sk2*o1.x + sk3*o1.y);
        }
        a0 += (double)s0;
        a1 += (double)s1;

        XA = XB; XB = Xn;
        e_m1 = e_0; e_0 = e_p1;
    }

    // warp reduction (deterministic)
    #pragma unroll
    for (int off = 16; off; off >>= 1) {
        a0 += __shfl_xor_sync(FULLM, a0, off);
        a1 += __shfl_xor_sync(FULLM, a1, off);
    }
    if (lane == 0) {
        g_part[w*2 + 0] = a0;
        g_part[w*2 + 1] = a1;
    }
}

// ---------------------------------------------------------------------------
__global__ void final_sum(float* __restrict__ out)
{
    __shared__ double sh[4][256];
    int t = threadIdx.x;
    double a[4] = {0, 0, 0, 0};
    for (int i = t; i < NWARP; i += 256) {
        int s = (i >> 10) & 1;       // image = i>>5; s = image>>5
        a[2*s + 0] += g_part[i*2 + 0];
        a[2*s + 1] += g_part[i*2 + 1];
    }
    for (int k = 0; k < 4; k++) sh[k][t] = a[k];
    __syncthreads();
    for (int off = 128; off; off >>= 1) {
        if (t < off)
            for (int k = 0; k < 4; k++) sh[k][t] += sh[k][t + off];
        __syncthreads();
    }
    if (t == 0) {
        // s=0: pred-skel sums (sum skel, sum skel*target)
        // s=1: target-skel sums (sum skel, sum skel*prob)
        double tprec = (sh[1][0] + 1.0) / (sh[0][0] + 1.0);
        double tsens = (sh[3][0] + 1.0) / (sh[2][0] + 1.0);
        double cl = 2.0 * tprec * tsens / (tprec + tsens + 1e-7);
        out[0] = (float)(1.0 - cl);
    }
}

// ---------------------------------------------------------------------------
extern "C" void kernel_launch(void* const* d_in, const int* in_sizes, int n_in,
                              void* d_out, int out_size)
{
    const float* pred = (const float*)d_in[0];
    const float* tgt  = (const float*)d_in[1];

    __half *h0, *eA, *eB;
    float  *P;
    cudaGetSymbolAddress((void**)&h0, g_h0);
    cudaGetSymbolAddress((void**)&eA, g_eA);
    cudaGetSymbolAddress((void**)&eB, g_eB);
    cudaGetSymbolAddress((void**)&P,  g_P);

    prep_kernel<<<2048, 256>>>(pred, tgt);

    dim3 grid(NWARP/4);   // 512 blocks, 4 warps each
    dim3 blk(128);

    pair_iter<<<grid, blk>>>(h0, P, eA, 1);   // d0,d1 ; out e2
    pair_iter<<<grid, blk>>>(eA, P, eB, 0);   // d2,d3 ; out e4
    pair_iter<<<grid, blk>>>(eB, P, eA, 0);   // d4,d5 ; out e6
    pair_iter<<<grid, blk>>>(eA, P, eB, 0);   // d6,d7 ; out e8
    pair_iter<<<grid, blk>>>(eB, P, eA, 0);   // d8,d9 ; out e10
    final_iter<<<grid, blk>>>(eA, P, h0);     // d10 + skel + reduction
    final_sum<<<1, 256>>>((float*)d_out);
}

// round 8
// speedup vs baseline: 8.0854x; 1.2404x over previous
#include <cuda_runtime.h>
#include <cuda_fp16.h>

#define HW    512
#define IMG   (HW*HW)
#define BATCH 32
#define NTOT  (BATCH*IMG)        // per stream
#define NWARP 4096               // 64 images * 64 stripes of 8 rows
#define FULLM 0xffffffffu

// __device__ scratch (no allocation allowed)
__device__ __align__(16) __half g_h0[2*NTOT];   // image i = s*32+b
__device__ __align__(16) __half g_eA[2*NTOT];
__device__ __align__(16) __half g_eB[2*NTOT];
__device__ __align__(16) float  g_P [2*NTOT];
__device__ double g_part[NWARP*2];

__device__ __forceinline__ int clampi(int v){ return v<0?0:(v>HW-1?HW-1:v); }

struct Row { __half2 h[8]; };    // 16 halves: lane covers gx [16*lane, 16*lane+15]

__device__ __forceinline__ unsigned h2u(__half2 x){ return *reinterpret_cast<unsigned*>(&x); }
__device__ __forceinline__ __half2  u2h(unsigned x){ return *reinterpret_cast<__half2*>(&x); }

__device__ __forceinline__ Row ld_row(const __half* base, int y, int xoff){
    const uint4* p = reinterpret_cast<const uint4*>(base + (size_t)clampi(y)*HW + xoff);
    uint4 a = p[0], b = p[1];
    Row r;
    r.h[0]=u2h(a.x); r.h[1]=u2h(a.y); r.h[2]=u2h(a.z); r.h[3]=u2h(a.w);
    r.h[4]=u2h(b.x); r.h[5]=u2h(b.y); r.h[6]=u2h(b.z); r.h[7]=u2h(b.w);
    return r;
}
__device__ __forceinline__ void st_row(__half* base, int y, int xoff, const Row& r){
    uint4 a, b;
    a.x=h2u(r.h[0]); a.y=h2u(r.h[1]); a.z=h2u(r.h[2]); a.w=h2u(r.h[3]);
    b.x=h2u(r.h[4]); b.y=h2u(r.h[5]); b.z=h2u(r.h[6]); b.w=h2u(r.h[7]);
    uint4* p = reinterpret_cast<uint4*>(base + (size_t)y*HW + xoff);
    p[0]=a; p[1]=b;
}

// horizontal 3-min over the 512-wide row; lane-boundary halves via shuffle;
// image x-edges use duplicated edge element (== SAME pad identity for min).
__device__ __forceinline__ Row hmin3_row(const Row& m, int lane){
    unsigned up = __shfl_up_sync(FULLM, h2u(m.h[7]), 1);
    unsigned dn = __shfl_down_sync(FULLM, h2u(m.h[0]), 1);
    __half L = (lane==0)  ? __low2half(m.h[0])  : __high2half(u2h(up));
    __half R = (lane==31) ? __high2half(m.h[7]) : __low2half(u2h(dn));
    Row o;
    #pragma unroll
    for (int i=0;i<8;i++){
        __half a = (i==0)? L : __high2half(m.h[i-1]);
        __half b = (i==7)? R : __low2half(m.h[i+1]);
        __half2 sl = __halves2half2(a, __low2half(m.h[i]));
        __half2 sr = __halves2half2(__high2half(m.h[i]), b);
        o.h[i] = __hmin2(__hmin2(sl, m.h[i]), sr);
    }
    return o;
}
__device__ __forceinline__ Row hmax3_row(const Row& m, int lane){
    unsigned up = __shfl_up_sync(FULLM, h2u(m.h[7]), 1);
    unsigned dn = __shfl_down_sync(FULLM, h2u(m.h[0]), 1);
    __half L = (lane==0)  ? __low2half(m.h[0])  : __high2half(u2h(up));
    __half R = (lane==31) ? __high2half(m.h[7]) : __low2half(u2h(dn));
    Row o;
    #pragma unroll
    for (int i=0;i<8;i++){
        __half a = (i==0)? L : __high2half(m.h[i-1]);
        __half b = (i==7)? R : __low2half(m.h[i+1]);
        __half2 sl = __halves2half2(a, __low2half(m.h[i]));
        __half2 sr = __halves2half2(__high2half(m.h[i]), b);
        o.h[i] = __hmax2(__hmax2(sl, m.h[i]), sr);
    }
    return o;
}

// erode = min(vert 3-min, horiz 3-min) (both windows include center)
__device__ __forceinline__ Row erode_row(const Row& up, const Row& md, const Row& dn, int lane){
    Row h = hmin3_row(md, lane);
    Row o;
    #pragma unroll
    for (int i=0;i<8;i++)
        o.h[i] = __hmin2(__hmin2(__hmin2(up.h[i], md.h[i]), dn.h[i]), h.h[i]);
    return o;
}
// dilate = 3x3 max, separable
__device__ __forceinline__ Row dilate_rows(const Row& a, const Row& b, const Row& c, int lane){
    Row v;
    #pragma unroll
    for (int i=0;i<8;i++) v.h[i] = __hmax2(__hmax2(a.h[i], b.h[i]), c.h[i]);
    return hmax3_row(v, lane);
}

// ---------------------------------------------------------------------------
__global__ void prep_kernel(const float* __restrict__ pred, const float* __restrict__ tgt) {
    int i = blockIdx.x * blockDim.x + threadIdx.x;
    int stride = gridDim.x * blockDim.x;
    const float4* p4 = (const float4*)pred;
    const float4* t4 = (const float4*)tgt;
    for (; i < NTOT/4; i += stride) {
        float4 p = p4[i];
        p.x = 1.f/(1.f+__expf(-p.x)); p.y = 1.f/(1.f+__expf(-p.y));
        p.z = 1.f/(1.f+__expf(-p.z)); p.w = 1.f/(1.f+__expf(-p.w));
        uint2 hp;
        hp.x = h2u(__floats2half2_rn(p.x, p.y));
        hp.y = h2u(__floats2half2_rn(p.z, p.w));
        *(uint2*)&g_h0[(size_t)4*i] = hp;
        float4 t = t4[i];
        uint2 ht;
        ht.x = h2u(__floats2half2_rn(t.x, t.y));
        ht.y = h2u(__floats2half2_rn(t.z, t.w));
        *(uint2*)&g_h0[(size_t)NTOT + 4*i] = ht;
    }
}

// ---------------------------------------------------------------------------
// pair_iter: two fused skeleton stages, register rolling pipeline, software
// pipelined X loads (4-deep window; fresh load consumed only next iteration).
// One warp sweeps an 8-row stripe of one image (full 512-px width).
//   e1 = erode(X); delta_a = relu(X - dilate(e1))
//   e2 = erode(e1); delta_b = relu(e1 - dilate(e2))
//   P[y] = (first ? 1 : P[y]) * (1-delta_a)*(1-delta_b);  Eout[y] = e2[y]
// ---------------------------------------------------------------------------
__global__ void __launch_bounds__(128, 3)
pair_iter(const __half* __restrict__ Xin, float* __restrict__ P,
          __half* __restrict__ Eout, int first)
{
    const int w     = blockIdx.x * 4 + (threadIdx.x >> 5);
    const int lane  = threadIdx.x & 31;
    const int image = w >> 6;              // 0..63
    const int y0    = (w & 63) << 3;       // 8-row stripe start
    const int xoff  = lane * 16;

    const __half* ptrX = Xin + (size_t)image * IMG;
    float*        ptrP = P   + (size_t)image * IMG;
    __half*       ptrE = Eout+ (size_t)image * IMG;

    // ---- prologue: X rows y0-3 .. y0+3 ----
    Row x_m3 = ld_row(ptrX, y0-3, xoff);
    Row x_m2 = ld_row(ptrX, y0-2, xoff);
    Row x_m1 = ld_row(ptrX, y0-1, xoff);
    Row XA   = ld_row(ptrX, y0  , xoff);   // X@y
    Row XB   = ld_row(ptrX, y0+1, xoff);   // X@y+1
    Row XC   = ld_row(ptrX, y0+2, xoff);   // X@y+2
    Row XD   = ld_row(ptrX, y0+3, xoff);   // X@y+3 (pipelined)

    Row e1_0  = erode_row(x_m1, XA, XB, lane);          // e1@y0
    Row e1_p1 = erode_row(XA, XB, XC, lane);            // e1@y0+1
    Row e1_m1, e1_m2;
    if (y0 == 0) { e1_m1 = e1_0; e1_m2 = e1_0; }
    else {
        e1_m1 = erode_row(x_m2, x_m1, XA, lane);        // e1@y0-1
        e1_m2 = erode_row(x_m3, x_m2, x_m1, lane);      // e1@y0-2
    }
    Row e2_0 = erode_row(e1_m1, e1_0, e1_p1, lane);     // e2@y0
    Row e2_m1;
    if (y0 == 0) e2_m1 = e2_0;
    else         e2_m1 = erode_row(e1_m2, e1_m1, e1_0, lane);

    #pragma unroll
    for (int k = 0; k < 8; ++k) {
        const int y = y0 + k;
        // issue next X load early; consumed only next iteration
        Row Xnext = ld_row(ptrX, y+4, xoff);

        Row e1n, e2n;
        if (y+2 <= HW-1) e1n = erode_row(XB, XC, XD, lane);        else e1n = e1_p1;
        if (y+1 <= HW-1) e2n = erode_row(e1_0, e1_p1, e1n, lane);  else e2n = e2_0;

        Row d1 = dilate_rows(e1_m1, e1_0, e1_p1, lane);
        Row d2 = dilate_rows(e2_m1, e2_0, e2n, lane);

        float* Prow = ptrP + (size_t)y * HW + xoff;
        #pragma unroll
        for (int i = 0; i < 8; i += 2) {
            float2 xa=__half22float2(XA.h[i]),   xb=__half22float2(XA.h[i+1]);
            float2 da=__half22float2(d1.h[i]),   db=__half22float2(d1.h[i+1]);
            float2 ea=__half22float2(e1_0.h[i]), eb=__half22float2(e1_0.h[i+1]);
            float2 ga=__half22float2(d2.h[i]),   gb=__half22float2(d2.h[i+1]);
            float4 pv;
            pv.x = (1.f - fmaxf(xa.x-da.x, 0.f)) * (1.f - fmaxf(ea.x-ga.x, 0.f));
            pv.y = (1.f - fmaxf(xa.y-da.y, 0.f)) * (1.f - fmaxf(ea.y-ga.y, 0.f));
            pv.z = (1.f - fmaxf(xb.x-db.x, 0.f)) * (1.f - fmaxf(eb.x-gb.x, 0.f));
            pv.w = (1.f - fmaxf(xb.y-db.y, 0.f)) * (1.f - fmaxf(eb.y-gb.y, 0.f));
            float4* pp = (float4*)(Prow + 2*i);
            if (!first) {
                float4 o = *pp;
                pv.x *= o.x; pv.y *= o.y; pv.z *= o.z; pv.w *= o.w;
            }
            *pp = pv;
        }
        st_row(ptrE, y, xoff, e2_0);

        // rotate windows
        XA = XB; XB = XC; XC = XD; XD = Xnext;
        e1_m1 = e1_0; e1_0 = e1_p1; e1_p1 = e1n;
        e2_m1 = e2_0; e2_0 = e2n;
    }
}

// ---------------------------------------------------------------------------
// final_iter: last stage (delta_10) + skel + per-warp reduction.
//   skel[y] = 1 - P[y]*(1 - relu(X[y]-dilate(erode(X))[y]))
//   a0 = sum(skel); a1 = sum(skel * other-stream h0)
// ---------------------------------------------------------------------------
__global__ void __launch_bounds__(128, 3)
final_iter(const __half* __restrict__ Xin, const float* __restrict__ P,
           const __half* __restrict__ H0)
{
    const int w     = blockIdx.x * 4 + (threadIdx.x >> 5);
    const int lane  = threadIdx.x & 31;
    const int image = w >> 6;
    const int y0    = (w & 63) << 3;
    const int xoff  = lane * 16;

    const __half* ptrX = Xin + (size_t)image * IMG;
    const float*  ptrP = P   + (size_t)image * IMG;
    const __half* ptrO = H0  + (size_t)(image ^ 32) * IMG;   // opposite stream

    Row x_m2 = ld_row(ptrX, y0-2, xoff);
    Row x_m1 = ld_row(ptrX, y0-1, xoff);
    Row XA   = ld_row(ptrX, y0,   xoff);   // X@y
    Row XB   = ld_row(ptrX, y0+1, xoff);   // X@y+1
    Row XC   = ld_row(ptrX, y0+2, xoff);   // X@y+2 (pipelined)

    Row e_0 = erode_row(x_m1, XA, XB, lane);             // e@y0
    Row e_m1;
    if (y0 == 0) e_m1 = e_0;
    else         e_m1 = erode_row(x_m2, x_m1, XA, lane); // e@y0-1

    double a0 = 0.0, a1 = 0.0;

    #pragma unroll
    for (int k = 0; k < 8; ++k) {
        const int y = y0 + k;
        Row Xnext = ld_row(ptrX, y+3, xoff);   // consumed next iteration

        Row e_p1;
        if (y+1 <= HW-1) e_p1 = erode_row(XA, XB, XC, lane); else e_p1 = e_0;
        Row d = dilate_rows(e_m1, e_0, e_p1, lane);

        const float* Prow = ptrP + (size_t)y * HW + xoff;
        const uint4* op   = reinterpret_cast<const uint4*>(ptrO + (size_t)y * HW + xoff);
        uint4 oa = op[0], ob = op[1];
        const unsigned ou[8] = {oa.x, oa.y, oa.z, oa.w, ob.x, ob.y, ob.z, ob.w};

        float s0 = 0.f, s1 = 0.f;
        #pragma unroll
        for (int i = 0; i < 8; i += 2) {
            float2 xa=__half22float2(XA.h[i]), xb=__half22float2(XA.h[i+1]);
            float2 da=__half22float2(d.h[i]),  db=__half22float2(d.h[i+1]);
            float4 Po = *(const float4*)(Prow + 2*i);
            float sk0 = 1.f - Po.x * (1.f - fmaxf(xa.x-da.x, 0.f));
            float sk1 = 1.f - Po.y * (1.f - fmaxf(xa.y-da.y, 0.f));
            float sk2 = 1.f - Po.z * (1.f - fmaxf(xb.x-db.x, 0.f));
            float sk3 = 1.f - Po.w * (1.f - fmaxf(xb.y-db.y, 0.f));
            float2 o0 = __half22float2(u2h(ou[i]));
            float2 o1 = __half22float2(u2h(ou[i+1]));
            s0 += (sk0 + sk1) + (sk2 + sk3);
            s1 += (sk0*o0.x + sk1*o0.y) + (sk2*o1.x + sk3*o1.y);
        }
        a0 += (double)s0;
        a1 += (double)s1;

        XA = XB; XB = XC; XC = Xnext;
        e_m1 = e_0; e_0 = e_p1;
    }

    // warp reduction (deterministic)
    #pragma unroll
    for (int off = 16; off; off >>= 1) {
        a0 += __shfl_xor_sync(FULLM, a0, off);
        a1 += __shfl_xor_sync(FULLM, a1, off);
    }
    if (lane == 0) {
        g_part[w*2 + 0] = a0;
        g_part[w*2 + 1] = a1;
    }
}

// ---------------------------------------------------------------------------
__global__ void final_sum(float* __restrict__ out)
{
    __shared__ double sh[4][256];
    int t = threadIdx.x;
    double a[4] = {0, 0, 0, 0};
    for (int i = t; i < NWARP; i += 256) {
        int s = (i >> 11) & 1;       // image = i>>6; s = image>>5
        a[2*s + 0] += g_part[i*2 + 0];
        a[2*s + 1] += g_part[i*2 + 1];
    }
    for (int k = 0; k < 4; k++) sh[k][t] = a[k];
    __syncthreads();
    for (int off = 128; off; off >>= 1) {
        if (t < off)
            for (int k = 0; k < 4; k++) sh[k][t] += sh[k][t + off];
        __syncthreads();
    }
    if (t == 0) {
        // s=0: pred-skel sums (sum skel, sum skel*target)
        // s=1: target-skel sums (sum skel, sum skel*prob)
        double tprec = (sh[1][0] + 1.0) / (sh[0][0] + 1.0);
        double tsens = (sh[3][0] + 1.0) / (sh[2][0] + 1.0);
        double cl = 2.0 * tprec * tsens / (tprec + tsens + 1e-7);
        out[0] = (float)(1.0 - cl);
    }
}

// ---------------------------------------------------------------------------
extern "C" void kernel_launch(void* const* d_in, const int* in_sizes, int n_in,
                              void* d_out, int out_size)
{
    const float* pred = (const float*)d_in[0];
    const float* tgt  = (const float*)d_in[1];

    __half *h0, *eA, *eB;
    float  *P;
    cudaGetSymbolAddress((void**)&h0, g_h0);
    cudaGetSymbolAddress((void**)&eA, g_eA);
    cudaGetSymbolAddress((void**)&eB, g_eB);
    cudaGetSymbolAddress((void**)&P,  g_P);

    prep_kernel<<<2048, 256>>>(pred, tgt);

    dim3 grid(NWARP/4);   // 1024 blocks, 4 warps each
    dim3 blk(128);

    pair_iter<<<grid, blk>>>(h0, P, eA, 1);   // d0,d1 ; out e2
    pair_iter<<<grid, blk>>>(eA, P, eB, 0);   // d2,d3 ; out e4
    pair_iter<<<grid, blk>>>(eB, P, eA, 0);   // d4,d5 ; out e6
    pair_iter<<<grid, blk>>>(eA, P, eB, 0);   // d6,d7 ; out e8
    pair_iter<<<grid, blk>>>(eB, P, eA, 0);   // d8,d9 ; out e10
    final_iter<<<grid, blk>>>(eA, P, h0);     // d10 + skel + reduction
    final_sum<<<1, 256>>>((float*)d_out);
}

// round 9
// speedup vs baseline: 13.7438x; 1.6998x over previous
#include <cuda_runtime.h>
#include <cuda_fp16.h>

#define HW    512
#define IMG   (HW*HW)
#define BATCH 32
#define NTOT  (BATCH*IMG)        // per stream
#define NWARP 4096               // 64 images * 64 stripes of 8 rows
#define FULLM 0xffffffffu

// __device__ scratch (no allocation allowed)
__device__ __align__(16) __half g_h0[2*NTOT];   // image i = s*32+b
__device__ __align__(16) __half g_eA[2*NTOT];
__device__ __align__(16) __half g_eB[2*NTOT];
__device__ __align__(16) __half g_P [2*NTOT];   // running product (1-skel), fp16
__device__ double g_part[NWARP*2];

__device__ __forceinline__ int clampi(int v){ return v<0?0:(v>HW-1?HW-1:v); }

struct Row { __half2 h[8]; };    // 16 halves: lane covers gx [16*lane, 16*lane+15]

__device__ __forceinline__ unsigned h2u(__half2 x){ return *reinterpret_cast<unsigned*>(&x); }
__device__ __forceinline__ __half2  u2h(unsigned x){ return *reinterpret_cast<__half2*>(&x); }

__device__ __forceinline__ Row ld_row(const __half* base, int y, int xoff){
    const uint4* p = reinterpret_cast<const uint4*>(base + (size_t)clampi(y)*HW + xoff);
    uint4 a = p[0], b = p[1];
    Row r;
    r.h[0]=u2h(a.x); r.h[1]=u2h(a.y); r.h[2]=u2h(a.z); r.h[3]=u2h(a.w);
    r.h[4]=u2h(b.x); r.h[5]=u2h(b.y); r.h[6]=u2h(b.z); r.h[7]=u2h(b.w);
    return r;
}
__device__ __forceinline__ void st_row(__half* base, int y, int xoff, const Row& r){
    uint4 a, b;
    a.x=h2u(r.h[0]); a.y=h2u(r.h[1]); a.z=h2u(r.h[2]); a.w=h2u(r.h[3]);
    b.x=h2u(r.h[4]); b.y=h2u(r.h[5]); b.z=h2u(r.h[6]); b.w=h2u(r.h[7]);
    uint4* p = reinterpret_cast<uint4*>(base + (size_t)y*HW + xoff);
    p[0]=a; p[1]=b;
}

// horizontal 3-min over the 512-wide row; lane-boundary halves via shuffle;
// image x-edges use duplicated edge element (== SAME pad identity for min).
__device__ __forceinline__ Row hmin3_row(const Row& m, int lane){
    unsigned up = __shfl_up_sync(FULLM, h2u(m.h[7]), 1);
    unsigned dn = __shfl_down_sync(FULLM, h2u(m.h[0]), 1);
    __half L = (lane==0)  ? __low2half(m.h[0])  : __high2half(u2h(up));
    __half R = (lane==31) ? __high2half(m.h[7]) : __low2half(u2h(dn));
    Row o;
    #pragma unroll
    for (int i=0;i<8;i++){
        __half a = (i==0)? L : __high2half(m.h[i-1]);
        __half b = (i==7)? R : __low2half(m.h[i+1]);
        __half2 sl = __halves2half2(a, __low2half(m.h[i]));
        __half2 sr = __halves2half2(__high2half(m.h[i]), b);
        o.h[i] = __hmin2(__hmin2(sl, m.h[i]), sr);
    }
    return o;
}
__device__ __forceinline__ Row hmax3_row(const Row& m, int lane){
    unsigned up = __shfl_up_sync(FULLM, h2u(m.h[7]), 1);
    unsigned dn = __shfl_down_sync(FULLM, h2u(m.h[0]), 1);
    __half L = (lane==0)  ? __low2half(m.h[0])  : __high2half(u2h(up));
    __half R = (lane==31) ? __high2half(m.h[7]) : __low2half(u2h(dn));
    Row o;
    #pragma unroll
    for (int i=0;i<8;i++){
        __half a = (i==0)? L : __high2half(m.h[i-1]);
        __half b = (i==7)? R : __low2half(m.h[i+1]);
        __half2 sl = __halves2half2(a, __low2half(m.h[i]));
        __half2 sr = __halves2half2(__high2half(m.h[i]), b);
        o.h[i] = __hmax2(__hmax2(sl, m.h[i]), sr);
    }
    return o;
}

// erode = min(vert 3-min, horiz 3-min) (both windows include center)
__device__ __forceinline__ Row erode_row(const Row& up, const Row& md, const Row& dn, int lane){
    Row h = hmin3_row(md, lane);
    Row o;
    #pragma unroll
    for (int i=0;i<8;i++)
        o.h[i] = __hmin2(__hmin2(__hmin2(up.h[i], md.h[i]), dn.h[i]), h.h[i]);
    return o;
}
// dilate = 3x3 max, separable
__device__ __forceinline__ Row dilate_rows(const Row& a, const Row& b, const Row& c, int lane){
    Row v;
    #pragma unroll
    for (int i=0;i<8;i++) v.h[i] = __hmax2(__hmax2(a.h[i], b.h[i]), c.h[i]);
    return hmax3_row(v, lane);
}

// ---------------------------------------------------------------------------
__global__ void prep_kernel(const float* __restrict__ pred, const float* __restrict__ tgt) {
    int i = blockIdx.x * blockDim.x + threadIdx.x;
    int stride = gridDim.x * blockDim.x;
    const float4* p4 = (const float4*)pred;
    const float4* t4 = (const float4*)tgt;
    for (; i < NTOT/4; i += stride) {
        float4 p = p4[i];
        p.x = 1.f/(1.f+__expf(-p.x)); p.y = 1.f/(1.f+__expf(-p.y));
        p.z = 1.f/(1.f+__expf(-p.z)); p.w = 1.f/(1.f+__expf(-p.w));
        uint2 hp;
        hp.x = h2u(__floats2half2_rn(p.x, p.y));
        hp.y = h2u(__floats2half2_rn(p.z, p.w));
        *(uint2*)&g_h0[(size_t)4*i] = hp;
        float4 t = t4[i];
        uint2 ht;
        ht.x = h2u(__floats2half2_rn(t.x, t.y));
        ht.y = h2u(__floats2half2_rn(t.z, t.w));
        *(uint2*)&g_h0[(size_t)NTOT + 4*i] = ht;
    }
}

// ---------------------------------------------------------------------------
// pair_iter: two fused skeleton stages, register rolling pipeline, software
// pipelined X loads. One warp sweeps an 8-row stripe (full 512-px width).
//   e1 = erode(X); delta_a = relu(X - dilate(e1))
//   e2 = erode(e1); delta_b = relu(e1 - dilate(e2))
//   P[y] = (first ? 1 : P[y]) * (1-delta_a)*(1-delta_b)   [all fp16 math]
//   Eout[y] = e2[y]
// ---------------------------------------------------------------------------
__global__ void __launch_bounds__(128, 4)
pair_iter(const __half* __restrict__ Xin, __half* __restrict__ P,
          __half* __restrict__ Eout, int first)
{
    const int w     = blockIdx.x * 4 + (threadIdx.x >> 5);
    const int lane  = threadIdx.x & 31;
    const int image = w >> 6;              // 0..63
    const int y0    = (w & 63) << 3;       // 8-row stripe start
    const int xoff  = lane * 16;

    const __half* ptrX = Xin + (size_t)image * IMG;
    __half*       ptrP = P   + (size_t)image * IMG;
    __half*       ptrE = Eout+ (size_t)image * IMG;

    const __half2 ONE2 = __floats2half2_rn(1.f, 1.f);
    const __half2 ZERO2 = __floats2half2_rn(0.f, 0.f);

    // ---- prologue: X rows y0-3 .. y0+3 ----
    Row x_m3 = ld_row(ptrX, y0-3, xoff);
    Row x_m2 = ld_row(ptrX, y0-2, xoff);
    Row x_m1 = ld_row(ptrX, y0-1, xoff);
    Row XA   = ld_row(ptrX, y0  , xoff);   // X@y
    Row XB   = ld_row(ptrX, y0+1, xoff);   // X@y+1
    Row XC   = ld_row(ptrX, y0+2, xoff);   // X@y+2
    Row XD   = ld_row(ptrX, y0+3, xoff);   // X@y+3 (pipelined)

    Row e1_0  = erode_row(x_m1, XA, XB, lane);          // e1@y0
    Row e1_p1 = erode_row(XA, XB, XC, lane);            // e1@y0+1
    Row e1_m1, e1_m2;
    if (y0 == 0) { e1_m1 = e1_0; e1_m2 = e1_0; }
    else {
        e1_m1 = erode_row(x_m2, x_m1, XA, lane);        // e1@y0-1
        e1_m2 = erode_row(x_m3, x_m2, x_m1, lane);      // e1@y0-2
    }
    Row e2_0 = erode_row(e1_m1, e1_0, e1_p1, lane);     // e2@y0
    Row e2_m1;
    if (y0 == 0) e2_m1 = e2_0;
    else         e2_m1 = erode_row(e1_m2, e1_m1, e1_0, lane);

    #pragma unroll
    for (int k = 0; k < 8; ++k) {
        const int y = y0 + k;
        // issue next X load early; consumed only next iteration
        Row Xnext = ld_row(ptrX, y+4, xoff);

        Row e1n, e2n;
        if (y+2 <= HW-1) e1n = erode_row(XB, XC, XD, lane);        else e1n = e1_p1;
        if (y+1 <= HW-1) e2n = erode_row(e1_0, e1_p1, e1n, lane);  else e2n = e2_0;

        Row d1 = dilate_rows(e1_m1, e1_0, e1_p1, lane);
        Row d2 = dilate_rows(e2_m1, e2_0, e2n, lane);

        // P update entirely in half2: pv = (1-relu(X-d1)) * (1-relu(e1-d2))
        Row pv;
        #pragma unroll
        for (int i = 0; i < 8; i++) {
            __half2 ta = __hsub2(ONE2, __hmax2(__hsub2(XA.h[i],   d1.h[i]), ZERO2));
            __half2 tb = __hsub2(ONE2, __hmax2(__hsub2(e1_0.h[i], d2.h[i]), ZERO2));
            pv.h[i] = __hmul2(ta, tb);
        }
        if (!first) {
            Row po = ld_row(ptrP, y, xoff);
            #pragma unroll
            for (int i = 0; i < 8; i++) pv.h[i] = __hmul2(pv.h[i], po.h[i]);
        }
        st_row(ptrP, y, xoff, pv);
        st_row(ptrE, y, xoff, e2_0);

        // rotate windows
        XA = XB; XB = XC; XC = XD; XD = Xnext;
        e1_m1 = e1_0; e1_0 = e1_p1; e1_p1 = e1n;
        e2_m1 = e2_0; e2_0 = e2n;
    }
}

// ---------------------------------------------------------------------------
// final_iter: last stage (delta_10) + skel + per-warp reduction.
//   skel[y] = 1 - P[y]*(1 - relu(X[y]-dilate(erode(X))[y]))
//   a0 = sum(skel); a1 = sum(skel * other-stream h0)
// ---------------------------------------------------------------------------
__global__ void __launch_bounds__(128, 4)
final_iter(const __half* __restrict__ Xin, const __half* __restrict__ P,
           const __half* __restrict__ H0)
{
    const int w     = blockIdx.x * 4 + (threadIdx.x >> 5);
    const int lane  = threadIdx.x & 31;
    const int image = w >> 6;
    const int y0    = (w & 63) << 3;
    const int xoff  = lane * 16;

    const __half* ptrX = Xin + (size_t)image * IMG;
    const __half* ptrP = P   + (size_t)image * IMG;
    const __half* ptrO = H0  + (size_t)(image ^ 32) * IMG;   // opposite stream

    const __half2 ONE2 = __floats2half2_rn(1.f, 1.f);
    const __half2 ZERO2 = __floats2half2_rn(0.f, 0.f);

    Row x_m2 = ld_row(ptrX, y0-2, xoff);
    Row x_m1 = ld_row(ptrX, y0-1, xoff);
    Row XA   = ld_row(ptrX, y0,   xoff);   // X@y
    Row XB   = ld_row(ptrX, y0+1, xoff);   // X@y+1
    Row XC   = ld_row(ptrX, y0+2, xoff);   // X@y+2 (pipelined)

    Row e_0 = erode_row(x_m1, XA, XB, lane);             // e@y0
    Row e_m1;
    if (y0 == 0) e_m1 = e_0;
    else         e_m1 = erode_row(x_m2, x_m1, XA, lane); // e@y0-1

    double a0 = 0.0, a1 = 0.0;

    #pragma unroll
    for (int k = 0; k < 8; ++k) {
        const int y = y0 + k;
        Row Xnext = ld_row(ptrX, y+3, xoff);   // consumed next iteration

        Row e_p1;
        if (y+1 <= HW-1) e_p1 = erode_row(XA, XB, XC, lane); else e_p1 = e_0;
        Row d = dilate_rows(e_m1, e_0, e_p1, lane);

        Row po = ld_row(ptrP, y, xoff);
        Row ov = ld_row(ptrO, y, xoff);

        float s0 = 0.f, s1 = 0.f;
        #pragma unroll
        for (int i = 0; i < 8; i++) {
            // skel = 1 - P*(1-delta), delta = relu(X-d)  [half2 then widen]
            __half2 t  = __hsub2(ONE2, __hmax2(__hsub2(XA.h[i], d.h[i]), ZERO2));
            __half2 sk = __hsub2(ONE2, __hmul2(po.h[i], t));
            float2 skf = __half22float2(sk);
            float2 of  = __half22float2(ov.h[i]);
            s0 += skf.x + skf.y;
            s1 += skf.x*of.x + skf.y*of.y;
        }
        a0 += (double)s0;
        a1 += (double)s1;

        XA = XB; XB = XC; XC = Xnext;
        e_m1 = e_0; e_0 = e_p1;
    }

    // warp reduction (deterministic)
    #pragma unroll
    for (int off = 16; off; off >>= 1) {
        a0 += __shfl_xor_sync(FULLM, a0, off);
        a1 += __shfl_xor_sync(FULLM, a1, off);
    }
    if (lane == 0) {
        g_part[w*2 + 0] = a0;
        g_part[w*2 + 1] = a1;
    }
}

// ---------------------------------------------------------------------------
__global__ void final_sum(float* __restrict__ out)
{
    __shared__ double sh[4][256];
    int t = threadIdx.x;
    double a[4] = {0, 0, 0, 0};
    for (int i = t; i < NWARP; i += 256) {
        int s = (i >> 11) & 1;       // image = i>>6; s = image>>5
        a[2*s + 0] += g_part[i*2 + 0];
        a[2*s + 1] += g_part[i*2 + 1];
    }
    for (int k = 0; k < 4; k++) sh[k][t] = a[k];
    __syncthreads();
    for (int off = 128; off; off >>= 1) {
        if (t < off)
            for (int k = 0; k < 4; k++) sh[k][t] += sh[k][t + off];
        __syncthreads();
    }
    if (t == 0) {
        // s=0: pred-skel sums (sum skel, sum skel*target)
        // s=1: target-skel sums (sum skel, sum skel*prob)
        double tprec = (sh[1][0] + 1.0) / (sh[0][0] + 1.0);
        double tsens = (sh[3][0] + 1.0) / (sh[2][0] + 1.0);
        double cl = 2.0 * tprec * tsens / (tprec + tsens + 1e-7);
        out[0] = (float)(1.0 - cl);
    }
}

// ---------------------------------------------------------------------------
extern "C" void kernel_launch(void* const* d_in, const int* in_sizes, int n_in,
                              void* d_out, int out_size)
{
    const float* pred = (const float*)d_in[0];
    const float* tgt  = (const float*)d_in[1];

    __half *h0, *eA, *eB, *P;
    cudaGetSymbolAddress((void**)&h0, g_h0);
    cudaGetSymbolAddress((void**)&eA, g_eA);
    cudaGetSymbolAddress((void**)&eB, g_eB);
    cudaGetSymbolAddress((void**)&P,  g_P);

    prep_kernel<<<2048, 256>>>(pred, tgt);

    dim3 grid(NWARP/4);   // 1024 blocks, 4 warps each
    dim3 blk(128);

    pair_iter<<<grid, blk>>>(h0, P, eA, 1);   // d0,d1 ; out e2
    pair_iter<<<grid, blk>>>(eA, P, eB, 0);   // d2,d3 ; out e4
    pair_iter<<<grid, blk>>>(eB, P, eA, 0);   // d4,d5 ; out e6
    pair_iter<<<grid, blk>>>(eA, P, eB, 0);   // d6,d7 ; out e8
    pair_iter<<<grid, blk>>>(eB, P, eA, 0);   // d8,d9 ; out e10
    final_iter<<<grid, blk>>>(eA, P, h0);     // d10 + skel + reduction
    final_sum<<<1, 256>>>((float*)d_out);
}